// round 9
// baseline (speedup 1.0000x reference)
#include <cuda_runtime.h>

#define NH 128
#define NI 64
#define NO 10
#define NB 128

// ---- packed f32x2 helpers (sm_100+ PTX) ----
__device__ __forceinline__ unsigned long long ffma2(unsigned long long a,
                                                    unsigned long long b,
                                                    unsigned long long c) {
    unsigned long long d;
    asm("fma.rn.f32x2 %0, %1, %2, %3;" : "=l"(d) : "l"(a), "l"(b), "l"(c));
    return d;
}
__device__ __forceinline__ unsigned long long addf2(unsigned long long a,
                                                    unsigned long long b) {
    unsigned long long d;
    asm("add.rn.f32x2 %0, %1, %2;" : "=l"(d) : "l"(a), "l"(b));
    return d;
}
__device__ __forceinline__ unsigned long long packf2(float lo, float hi) {
    unsigned long long r;
    asm("mov.b64 %0, {%1, %2};" : "=l"(r) : "f"(lo), "f"(hi));
    return r;
}
__device__ __forceinline__ float2 unpackf2(unsigned long long v) {
    float2 f;
    asm("mov.b64 {%0, %1}, %2;" : "=f"(f.x), "=f"(f.y) : "l"(v));
    return f;
}

// ============================================================
// Fused persistent RNN: grid = NB (1 chain/SM), block = 256.
// Warps 0-3: R6 scan body verbatim (warp w = K-slice [32w,32w+32),
//   lane l -> partials for columns 4l..4l+3; one __syncthreads/step;
//   reduce column tid; fdividef tanh).
// Warps 4-7 (producers): thread j = tid-128 owns xw column j.
//   At step t they compute xw[t+2] = x[t+2] @ Wxh[:,j] from a shared
//   x-ring and deposit into a shared xw-ring; x-ring rotated via LDG
//   3 steps ahead. Scan phase A reads xw[t] with one LDS.32 written
//   two barriers earlier. Producers arrive at the barrier early ->
//   no added skew; scan critical path untouched; kernel K1 removed.
// ============================================================
__global__ void __launch_bounds__(256, 1) rnn_fused_kernel(
    const float* __restrict__ x,    // [S, B, NI]
    const float* __restrict__ Wxh,  // [NI, NH]
    const float* __restrict__ Whh,  // [NH, NH]
    const float* __restrict__ Why,  // [NH, NO]
    const float* __restrict__ bh,   // [NH]
    const float* __restrict__ by,   // [NO]
    float* __restrict__ out,        // logits [B,NO] then h [S,B,NH]
    int seq)
{
    const int b   = blockIdx.x;
    const int tid = threadIdx.x;
    const int w   = tid >> 5;
    const int l   = tid & 31;
    const bool scan_role = (w < 4);

    __shared__ __align__(16) float hsh[2][NH];       // parity-swapped h
    __shared__ __align__(16) float part[2][4][NH];   // double-buffered partials
    __shared__ __align__(16) float xwsh[4][NH];      // xw ring
    __shared__ __align__(16) float xring[4][NI];     // raw x ring

    // ---------------- per-role setup ----------------
    // scan warps: Whh slices. wp[c][kk] packs Whh[k][4l+c],
    // k-pair (32w+2kk, 32w+2kk+1).
    unsigned long long wp[4][16];
    // producer warps: Wxh column j. wx2[q] packs Wxh[2q][j], Wxh[2q+1][j].
    unsigned long long wx2[NI / 2];
    float xr = 0.0f;     // producer lanes j<64: in-flight x element
    float bias = 0.0f;

    if (scan_role) {
#pragma unroll
        for (int c = 0; c < 4; c++) {
            const int col = 4 * l + c;
#pragma unroll
            for (int kk = 0; kk < 16; kk++) {
                const int k = 32 * w + 2 * kk;
                wp[c][kk] = packf2(Whh[k * NH + col], Whh[(k + 1) * NH + col]);
            }
        }
        bias = bh[tid];
        hsh[0][tid] = 0.0f;
    } else {
        const int j = tid - 128;
#pragma unroll
        for (int q = 0; q < NI / 2; q++)
            wx2[q] = packf2(Wxh[(2 * q) * NH + j], Wxh[(2 * q + 1) * NH + j]);
        // prime x ring with x[0..3]; xr holds x[4]
        if (j < NI) {
#pragma unroll
            for (int q = 0; q < 4; q++) {
                int tq = (q < seq) ? q : (seq - 1);
                xring[q][j] = x[((long long)tq * NB + b) * NI + j];
            }
            int t4 = (4 < seq) ? 4 : (seq - 1);
            xr = x[((long long)t4 * NB + b) * NI + j];
        }
    }
    __syncthreads();

    // producers: bootstrap xw[0], xw[1]
    if (!scan_role) {
        const int j = tid - 128;
#pragma unroll
        for (int q = 0; q < 2; q++) {
            const ulonglong2* xv =
                reinterpret_cast<const ulonglong2*>(xring[q]);
            unsigned long long a0 = 0ull, a1 = 0ull, a2 = 0ull, a3 = 0ull;
#pragma unroll
            for (int m = 0; m < NI / 4; m++) {
                ulonglong2 v = xv[m];
                if (m & 1) { a2 = ffma2(v.x, wx2[2 * m], a2); a3 = ffma2(v.y, wx2[2 * m + 1], a3); }
                else       { a0 = ffma2(v.x, wx2[2 * m], a0); a1 = ffma2(v.y, wx2[2 * m + 1], a1); }
            }
            float2 f = unpackf2(addf2(addf2(a0, a1), addf2(a2, a3)));
            xwsh[q][j] = f.x + f.y;
        }
    }
    __syncthreads();

    float* h_out = out + NB * NO;

#pragma unroll 2
    for (int t = 0; t < seq; t++) {
        const int pb = t & 1;

        if (scan_role) {
            // ---- phase A: xw pickup + own h slice + partials (R6 body) ----
            const float xwv = xwsh[t & 3][tid];   // written 2 barriers ago

            ulonglong2 hv[8];
            const ulonglong2* h2 =
                reinterpret_cast<const ulonglong2*>(&hsh[pb][32 * w]);
#pragma unroll
            for (int m = 0; m < 8; m++) hv[m] = h2[m];

            unsigned long long a0 = 0ull, a1 = 0ull, a2 = 0ull, a3 = 0ull;
#pragma unroll
            for (int m = 0; m < 8; m++) {
                a0 = ffma2(hv[m].x, wp[0][2 * m], a0);
                a0 = ffma2(hv[m].y, wp[0][2 * m + 1], a0);
                a1 = ffma2(hv[m].x, wp[1][2 * m], a1);
                a1 = ffma2(hv[m].y, wp[1][2 * m + 1], a1);
                a2 = ffma2(hv[m].x, wp[2][2 * m], a2);
                a2 = ffma2(hv[m].y, wp[2][2 * m + 1], a2);
                a3 = ffma2(hv[m].x, wp[3][2 * m], a3);
                a3 = ffma2(hv[m].y, wp[3][2 * m + 1], a3);
            }
            float2 f0 = unpackf2(a0), f1 = unpackf2(a1),
                   f2 = unpackf2(a2), f3 = unpackf2(a3);
            float4 pr = make_float4(f0.x + f0.y, f1.x + f1.y,
                                    f2.x + f2.y, f3.x + f3.y);
            *reinterpret_cast<float4*>(&part[pb][w][4 * l]) = pr;

            __syncthreads();   // partial exchange (the only block barrier)

            // ---- phase B: reduce + tanh + h write ----
            float v = ((part[pb][0][tid] + part[pb][1][tid]) +
                       (part[pb][2][tid] + part[pb][3][tid])) + xwv + bias;

            float a = fabsf(v);
            float e = __expf(-2.0f * a);
            float r = __fdividef(1.0f - e, 1.0f + e);
            float h = copysignf(r, v);

            h_out[((long long)t * NB + b) * NH + tid] = h;
            hsh[pb ^ 1][tid] = h;   // own consumed slice re-written
            __syncwarp();
        } else {
            // ---- producer: xw[t+2] from x-ring, rotate x-ring ----
            const int j = tid - 128;
            const ulonglong2* xv =
                reinterpret_cast<const ulonglong2*>(xring[(t + 2) & 3]);
            unsigned long long a0 = 0ull, a1 = 0ull, a2 = 0ull, a3 = 0ull;
#pragma unroll
            for (int m = 0; m < NI / 4; m++) {
                ulonglong2 v = xv[m];
                if (m & 1) { a2 = ffma2(v.x, wx2[2 * m], a2); a3 = ffma2(v.y, wx2[2 * m + 1], a3); }
                else       { a0 = ffma2(v.x, wx2[2 * m], a0); a1 = ffma2(v.y, wx2[2 * m + 1], a1); }
            }
            float2 f = unpackf2(addf2(addf2(a0, a1), addf2(a2, a3)));
            xwsh[(t + 2) & 3][j] = f.x + f.y;   // consumed at step t+2

            if (j < NI) {
                xring[(t + 4) & 3][j] = xr;      // x[t+4]; old x[t] is dead
                int tf = t + 5;
                if (tf >= seq) tf = seq - 1;
                xr = x[((long long)tf * NB + b) * NI + j];
            }
            __syncthreads();
            // (no phase-B work for producers)
        }
    }

    __syncthreads();
    // ---- logits = h_last @ Why + by ----
    if (tid < NO) {
        float acc = by[tid];
#pragma unroll 8
        for (int k = 0; k < NH; k++)
            acc = fmaf(hsh[seq & 1][k], Why[k * NO + tid], acc);
        out[b * NO + tid] = acc;
    }
}

extern "C" void kernel_launch(void* const* d_in, const int* in_sizes, int n_in,
                              void* d_out, int out_size) {
    const float* x   = (const float*)d_in[0];
    const float* Wxh = (const float*)d_in[1];
    const float* Whh = (const float*)d_in[2];
    const float* Why = (const float*)d_in[3];
    const float* bh  = (const float*)d_in[4];
    const float* by  = (const float*)d_in[5];
    float* out = (float*)d_out;

    int seq = in_sizes[0] / (NB * NI);  // 2048

    rnn_fused_kernel<<<NB, 256>>>(x, Wxh, Whh, Why, bh, by, out, seq);
}

// round 10
// speedup vs baseline: 1.2289x; 1.2289x over previous
#include <cuda_runtime.h>

#define NH 128
#define NI 64
#define NO 10
#define NB 128
#define S_MAX 2048

// 128 MiB scratch for the precomputed input projection xW[S,B,H].
__device__ __align__(16) float g_xw[(size_t)S_MAX * NB * NH];

// ---- packed f32x2 helpers (sm_100+ PTX) ----
__device__ __forceinline__ unsigned long long ffma2(unsigned long long a,
                                                    unsigned long long b,
                                                    unsigned long long c) {
    unsigned long long d;
    asm("fma.rn.f32x2 %0, %1, %2, %3;" : "=l"(d) : "l"(a), "l"(b), "l"(c));
    return d;
}
__device__ __forceinline__ unsigned long long addf2(unsigned long long a,
                                                    unsigned long long b) {
    unsigned long long d;
    asm("add.rn.f32x2 %0, %1, %2;" : "=l"(d) : "l"(a), "l"(b));
    return d;
}
__device__ __forceinline__ unsigned long long packf2(float lo, float hi) {
    unsigned long long r;
    asm("mov.b64 %0, {%1, %2};" : "=l"(r) : "f"(lo), "f"(hi));
    return r;
}
__device__ __forceinline__ float2 unpackf2(unsigned long long v) {
    float2 f;
    asm("mov.b64 {%0, %1}, %2;" : "=f"(f.x), "=f"(f.y) : "l"(v));
    return f;
}

// ============================================================
// K1 (R7 verbatim): xW[s,b,j] = x[s,b,:] @ Wxh[:,j] + bh[j]
// grid = (seq, 8): CTA handles 16 batch rows. block = 128.
// ============================================================
__global__ void __launch_bounds__(128, 1) xw_gemm_kernel(
    const float* __restrict__ x, const float* __restrict__ Wxh,
    const float* __restrict__ bh, int seq)
{
    const int s = blockIdx.x;
    const int bbase = blockIdx.y * 16;
    __shared__ __align__(16) float xs[16 * NI];  // 4 KB

    const float4* xin =
        reinterpret_cast<const float4*>(x + ((long long)s * NB + bbase) * NI);
    float4* xs4 = reinterpret_cast<float4*>(xs);
#pragma unroll
    for (int i = threadIdx.x; i < 16 * NI / 4; i += 128) xs4[i] = xin[i];

    const int j = threadIdx.x;

    unsigned long long w2[NI / 2];
#pragma unroll
    for (int m = 0; m < NI / 2; m++)
        w2[m] = packf2(Wxh[(2 * m) * NH + j], Wxh[(2 * m + 1) * NH + j]);
    const unsigned long long bias2 = packf2(bh[j], 0.0f);
    __syncthreads();

#pragma unroll
    for (int b = 0; b < 16; b++) {
        const ulonglong2* xr = reinterpret_cast<const ulonglong2*>(xs + b * NI);
        unsigned long long a0 = bias2, a1 = 0ull, a2 = 0ull, a3 = 0ull;
#pragma unroll
        for (int m = 0; m < NI / 4; m++) {
            ulonglong2 xv = xr[m];
            if (m & 1) { a2 = ffma2(xv.x, w2[2 * m], a2); a3 = ffma2(xv.y, w2[2 * m + 1], a3); }
            else       { a0 = ffma2(xv.x, w2[2 * m], a0); a1 = ffma2(xv.y, w2[2 * m + 1], a1); }
        }
        float2 f = unpackf2(addf2(addf2(a0, a1), addf2(a2, a3)));
        g_xw[((long long)s * NB + bbase + b) * NH + j] = f.x + f.y;
    }
}

// ============================================================
// K2 (R6 verbatim): sequential scan with K-split partial exchange.
// grid = NB (1 chain per CTA/SM), block = 128.
// Warp w owns columns [32w,32w+32) AND K-slice [32w,32w+32).
// tanh via exp + __fdividef (MUFU.RCP; denominator in [1,2] -> ~2 ulp).
// ============================================================
__global__ void __launch_bounds__(NH, 1) rnn_scan_kernel(
    const float* __restrict__ Whh, const float* __restrict__ Why,
    const float* __restrict__ bh, const float* __restrict__ by,
    float* __restrict__ out, int seq)
{
    const int b   = blockIdx.x;
    const int tid = threadIdx.x;
    const int w   = tid >> 5;   // warp = K-slice index
    const int l   = tid & 31;

    // Weights: wp[c][kk] packs Whh[k][4l+c] for k-pair (32w+2kk, 32w+2kk+1).
    unsigned long long wp[4][16];
#pragma unroll
    for (int c = 0; c < 4; c++) {
        const int col = 4 * l + c;
#pragma unroll
        for (int kk = 0; kk < 16; kk++) {
            const int k = 32 * w + 2 * kk;
            wp[c][kk] = packf2(Whh[k * NH + col], Whh[(k + 1) * NH + col]);
        }
    }
    const float bias = bh[tid];

    __shared__ __align__(16) float hbuf[2][NH];        // parity-swapped h
    __shared__ __align__(16) float part[2][4][NH];     // double-buffered partials
    hbuf[0][tid] = 0.0f;

    // xw prefetch ring (depth 4) for OWN column tid
    const float* xwb = g_xw + (long long)b * NH + tid;
    float xq[4];
#pragma unroll
    for (int q = 0; q < 4; q++)
        xq[q] = (q < seq) ? xwb[(long long)q * NB * NH] : 0.0f;

    float* h_out = out + NB * NO;
    __syncthreads();

#pragma unroll 4
    for (int t = 0; t < seq; t++) {
        const int pb = t & 1;

        // ---- batched load of OWN warp's h slice (8 broadcast LDS.128) ----
        ulonglong2 hv[8];
        const ulonglong2* h2 =
            reinterpret_cast<const ulonglong2*>(&hbuf[pb][32 * w]);
#pragma unroll
        for (int m = 0; m < 8; m++) hv[m] = h2[m];

        // ---- 32-term partials for columns 4l..4l+3 (64 FFMA2) ----
        unsigned long long a0 = 0ull, a1 = 0ull, a2 = 0ull, a3 = 0ull;
#pragma unroll
        for (int m = 0; m < 8; m++) {
            a0 = ffma2(hv[m].x, wp[0][2 * m], a0);
            a0 = ffma2(hv[m].y, wp[0][2 * m + 1], a0);
            a1 = ffma2(hv[m].x, wp[1][2 * m], a1);
            a1 = ffma2(hv[m].y, wp[1][2 * m + 1], a1);
            a2 = ffma2(hv[m].x, wp[2][2 * m], a2);
            a2 = ffma2(hv[m].y, wp[2][2 * m + 1], a2);
            a3 = ffma2(hv[m].x, wp[3][2 * m], a3);
            a3 = ffma2(hv[m].y, wp[3][2 * m + 1], a3);
        }
        float2 f0 = unpackf2(a0), f1 = unpackf2(a1),
               f2 = unpackf2(a2), f3 = unpackf2(a3);
        float4 pr = make_float4(f0.x + f0.y, f1.x + f1.y,
                                f2.x + f2.y, f3.x + f3.y);
        *reinterpret_cast<float4*>(&part[pb][w][4 * l]) = pr;  // conflict-free

        // xw consume + refill (covers DRAM latency across 4 steps)
        const float xwv = xq[t & 3];
        if (t + 4 < seq) xq[t & 3] = xwb[(long long)(t + 4) * NB * NH];

        __syncthreads();

        // ---- reduce 4 partials for OWN column tid ----
        float v = ((part[pb][0][tid] + part[pb][1][tid]) +
                   (part[pb][2][tid] + part[pb][3][tid])) + xwv + bias;

        // tanh: exp2 + fast reciprocal (denominator in [1,2] -> ~2 ulp).
        float a = fabsf(v);
        float e = __expf(-2.0f * a);
        float r = __fdividef(1.0f - e, 1.0f + e);
        float h = copysignf(r, v);

        h_out[((long long)t * NB + b) * NH + tid] = h;  // coalesced 512 B
        hbuf[pb ^ 1][tid] = h;   // own-warp slice; next step reads own slice only
        __syncwarp();
    }

    __syncthreads();
    // ---- logits = h_last @ Why + by ----
    if (tid < NO) {
        float acc = by[tid];
#pragma unroll 8
        for (int k = 0; k < NH; k++)
            acc = fmaf(hbuf[seq & 1][k], Why[k * NO + tid], acc);
        out[b * NO + tid] = acc;
    }
}

extern "C" void kernel_launch(void* const* d_in, const int* in_sizes, int n_in,
                              void* d_out, int out_size) {
    const float* x   = (const float*)d_in[0];
    const float* Wxh = (const float*)d_in[1];
    const float* Whh = (const float*)d_in[2];
    const float* Why = (const float*)d_in[3];
    const float* bh  = (const float*)d_in[4];
    const float* by  = (const float*)d_in[5];
    float* out = (float*)d_out;

    int seq = in_sizes[0] / (NB * NI);  // 2048
    if (seq > S_MAX) seq = S_MAX;

    dim3 g1(seq, 8);
    xw_gemm_kernel<<<g1, 128>>>(x, Wxh, bh, seq);
    rnn_scan_kernel<<<NB, NH>>>(Whh, Why, bh, by, out, seq);
}